// round 1
// baseline (speedup 1.0000x reference)
#include <cuda_runtime.h>

#define N_MAX 50000
#define IN_FEATS 128
#define HF 64

// Scratch (device globals; no allocation allowed)
__device__ float g_deg[N_MAX];
__device__ float g_dinv[N_MAX];
__device__ float g_x[N_MAX * HF];    // f0 = relu(F W1^T + b1)
__device__ float g_f1[N_MAX * HF];   // f1 = L f0
__device__ float g_agg[N_MAX * HF];  // scatter accumulator; ends as f2 = L f1
__device__ float g_M[HF * 192];      // folded W2

// ---------------------------------------------------------------------------
__global__ void zero_kernel(int n) {
    int i = blockIdx.x * blockDim.x + threadIdx.x;
    int total = n * 16;  // float4 count of g_agg
    float4 z = make_float4(0.f, 0.f, 0.f, 0.f);
    if (i < total) reinterpret_cast<float4*>(g_agg)[i] = z;
    if (i < n) g_deg[i] = 0.f;
}

__global__ void deg_kernel(const int* __restrict__ dst, int e) {
    int i = blockIdx.x * blockDim.x + threadIdx.x;
    if (i < e) atomicAdd(&g_deg[dst[i]], 1.0f);
}

__global__ void dinv_kernel(int n) {
    int i = blockIdx.x * blockDim.x + threadIdx.x;
    if (i < n) g_dinv[i] = rsqrtf(fmaxf(g_deg[i], 1.0f));
}

// ---------------------------------------------------------------------------
// GEMM1: x = relu(features[n,128] @ W1[64,128]^T + b1)
__global__ __launch_bounds__(128) void gemm1_kernel(
    const float* __restrict__ A, const float* __restrict__ W1,
    const float* __restrict__ b1, int n) {
    __shared__ float As[32][129];
    __shared__ float Bs[32][65];
    int t = threadIdx.x;
    int m0 = blockIdx.x * 128;
    int tx = t & 7, ty = t >> 3;  // tx: 8 n-groups, ty: 16 m-groups

    float acc[8][8];
#pragma unroll
    for (int i = 0; i < 8; i++)
#pragma unroll
        for (int j = 0; j < 8; j++) acc[i][j] = 0.f;

    for (int k0 = 0; k0 < IN_FEATS; k0 += 32) {
#pragma unroll
        for (int i = 0; i < 32; i++) {
            int e = t + i * 128;
            int m = e >> 5, k = e & 31;
            int gm = m0 + m;
            float v = 0.f;
            if (gm < n) v = A[gm * IN_FEATS + k0 + k];
            As[k][m] = v;
        }
#pragma unroll
        for (int i = 0; i < 16; i++) {
            int e = t + i * 128;
            int nn = e >> 5, k = e & 31;
            Bs[k][nn] = W1[nn * IN_FEATS + k0 + k];
        }
        __syncthreads();
#pragma unroll
        for (int k = 0; k < 32; k++) {
            float a[8], b[8];
#pragma unroll
            for (int i = 0; i < 8; i++) a[i] = As[k][ty * 8 + i];
#pragma unroll
            for (int j = 0; j < 8; j++) b[j] = Bs[k][tx * 8 + j];
#pragma unroll
            for (int i = 0; i < 8; i++)
#pragma unroll
                for (int j = 0; j < 8; j++)
                    acc[i][j] = fmaf(a[i], b[j], acc[i][j]);
        }
        __syncthreads();
    }
#pragma unroll
    for (int i = 0; i < 8; i++) {
        int gm = m0 + ty * 8 + i;
        if (gm < n) {
#pragma unroll
            for (int j = 0; j < 8; j++) {
                float v = acc[i][j] + b1[tx * 8 + j];
                g_x[gm * HF + tx * 8 + j] = v > 0.f ? v : 0.f;
            }
        }
    }
}

// ---------------------------------------------------------------------------
// Scatter: g_agg[dst] += dinv[src] * f[src]   (64 floats/edge, 16 lanes/edge)
__global__ void scatter_kernel(const int* __restrict__ src,
                               const int* __restrict__ dst,
                               int e, int use_f1) {
    int t = blockIdx.x * blockDim.x + threadIdx.x;
    if (t >= e * 16) return;
    int ed = t >> 4, c = t & 15;
    int s = src[ed];
    int d = dst[ed];
    float w = g_dinv[s];
    const float4* fsrc = reinterpret_cast<const float4*>(use_f1 ? g_f1 : g_x);
    float4 v = fsrc[s * 16 + c];
    float* p = &g_agg[(d * 16 + c) * 4];
    asm volatile("red.global.add.v4.f32 [%0], {%1,%2,%3,%4};"
                 :: "l"(p), "f"(v.x * w), "f"(v.y * w), "f"(v.z * w), "f"(v.w * w)
                 : "memory");
}

// Combine: fout = fin - dinv * agg; optionally rezero agg for the next scatter.
// step 0: f1 = x - dinv*agg (zero agg);  step 1: agg <- f2 = f1 - dinv*agg (in place)
__global__ void combine_kernel(int n, int step) {
    int i = blockIdx.x * blockDim.x + threadIdx.x;
    if (i >= n * 16) return;
    int node = i >> 4;
    float w = g_dinv[node];
    float4* aggp = reinterpret_cast<float4*>(g_agg);
    float4 a = aggp[i];
    const float4* fin = reinterpret_cast<const float4*>(step == 0 ? g_x : g_f1);
    float4 x = fin[i];
    float4 r = make_float4(x.x - w * a.x, x.y - w * a.y,
                           x.z - w * a.z, x.w - w * a.w);
    if (step == 0) {
        reinterpret_cast<float4*>(g_f1)[i] = r;
        aggp[i] = make_float4(0.f, 0.f, 0.f, 0.f);
    } else {
        aggp[i] = r;  // g_agg now holds f2
    }
}

// ---------------------------------------------------------------------------
// Fold thetas into W2: M[r][p*64+c] = sum_j THETA[j][p] * W2[r][j*64+c]
__global__ void buildM_kernel(const float* __restrict__ W2) {
    int t = blockIdx.x * blockDim.x + threadIdx.x;
    if (t >= HF * 192) return;
    int r = t / 192, k = t % 192;
    int p = k >> 6, c = k & 63;
    // THETA[0] = {3, -3, 0.75}; THETA[1] = {0, 3, -1.5}; THETA[2] = {0, 0, 0.75}
    const float cA[3] = {3.0f, -3.0f, 0.75f};
    const float cB[3] = {0.0f, 3.0f, -1.5f};
    const float cC[3] = {0.0f, 0.0f, 0.75f};
    g_M[t] = cA[p] * W2[r * 192 + c]
           + cB[p] * W2[r * 192 + 64 + c]
           + cC[p] * W2[r * 192 + 128 + c];
}

// GEMM2: out = [x | f1 | f2] @ M^T + b2   (K=192, f2 lives in g_agg)
__global__ __launch_bounds__(128) void gemm2_kernel(
    const float* __restrict__ b2, float* __restrict__ out, int n) {
    __shared__ float As[32][129];
    __shared__ float Bs[32][65];
    int t = threadIdx.x;
    int m0 = blockIdx.x * 128;
    int tx = t & 7, ty = t >> 3;

    float acc[8][8];
#pragma unroll
    for (int i = 0; i < 8; i++)
#pragma unroll
        for (int j = 0; j < 8; j++) acc[i][j] = 0.f;

#pragma unroll
    for (int cch = 0; cch < 6; cch++) {
        const float* S = (cch < 2) ? g_x : (cch < 4) ? g_f1 : g_agg;
        int koff = (cch & 1) * 32;
#pragma unroll
        for (int i = 0; i < 32; i++) {
            int e = t + i * 128;
            int m = e >> 5, k = e & 31;
            int gm = m0 + m;
            float v = 0.f;
            if (gm < n) v = S[gm * HF + koff + k];
            As[k][m] = v;
        }
#pragma unroll
        for (int i = 0; i < 16; i++) {
            int e = t + i * 128;
            int nn = e >> 5, k = e & 31;
            Bs[k][nn] = g_M[nn * 192 + cch * 32 + k];
        }
        __syncthreads();
#pragma unroll
        for (int k = 0; k < 32; k++) {
            float a[8], b[8];
#pragma unroll
            for (int i = 0; i < 8; i++) a[i] = As[k][ty * 8 + i];
#pragma unroll
            for (int j = 0; j < 8; j++) b[j] = Bs[k][tx * 8 + j];
#pragma unroll
            for (int i = 0; i < 8; i++)
#pragma unroll
                for (int j = 0; j < 8; j++)
                    acc[i][j] = fmaf(a[i], b[j], acc[i][j]);
        }
        __syncthreads();
    }
#pragma unroll
    for (int i = 0; i < 8; i++) {
        int gm = m0 + ty * 8 + i;
        if (gm < n) {
#pragma unroll
            for (int j = 0; j < 8; j++)
                out[gm * HF + tx * 8 + j] = acc[i][j] + b2[tx * 8 + j];
        }
    }
}

// ---------------------------------------------------------------------------
extern "C" void kernel_launch(void* const* d_in, const int* in_sizes, int n_in,
                              void* d_out, int out_size) {
    const float* features = (const float*)d_in[0];
    const int*   src      = (const int*)d_in[1];
    const int*   dst      = (const int*)d_in[2];
    const float* W1       = (const float*)d_in[3];
    const float* b1       = (const float*)d_in[4];
    const float* W2       = (const float*)d_in[5];
    const float* b2       = (const float*)d_in[6];
    float* out = (float*)d_out;

    int n = in_sizes[0] / IN_FEATS;   // 50000
    int e = in_sizes[1];              // 800000

    int zt = n * 16;
    zero_kernel<<<(zt + 255) / 256, 256>>>(n);
    deg_kernel<<<(e + 255) / 256, 256>>>(dst, e);
    dinv_kernel<<<(n + 255) / 256, 256>>>(n);

    gemm1_kernel<<<(n + 127) / 128, 128>>>(features, W1, b1, n);
    buildM_kernel<<<(HF * 192 + 255) / 256, 256>>>(W2);

    int st = e * 16;
    scatter_kernel<<<(st + 255) / 256, 256>>>(src, dst, e, 0);  // agg = A~ x
    combine_kernel<<<(zt + 255) / 256, 256>>>(n, 0);            // f1, agg=0
    scatter_kernel<<<(st + 255) / 256, 256>>>(src, dst, e, 1);  // agg = A~ f1
    combine_kernel<<<(zt + 255) / 256, 256>>>(n, 1);            // agg <- f2

    gemm2_kernel<<<(n + 127) / 128, 128>>>(b2, out, n);
}

// round 3
// speedup vs baseline: 1.6149x; 1.6149x over previous
#include <cuda_runtime.h>

#define N_MAX 50000
#define E_MAX 800000
#define IN_FEATS 128
#define HF 64

// Scratch (device globals; no allocation allowed)
__device__ int   g_cnt[N_MAX];
__device__ int   g_off[N_MAX + 1];
__device__ int   g_cur[N_MAX];
__device__ int   g_bsum[256];
__device__ int   g_esrc[E_MAX];
__device__ float g_dinv[N_MAX];
__device__ float g_x[N_MAX * HF];
__device__ float g_f1[N_MAX * HF];
__device__ float g_f2[N_MAX * HF];
__device__ float g_M[HF * 192];

// ---------------------------------------------------------------------------
__global__ void zero_cnt_kernel(int n) {
    int i = blockIdx.x * blockDim.x + threadIdx.x;
    if (i < n) g_cnt[i] = 0;
}

__global__ void count_kernel(const int* __restrict__ dst, int e) {
    int i = blockIdx.x * blockDim.x + threadIdx.x;
    if (i < e) atomicAdd(&g_cnt[dst[i]], 1);
}

__global__ void dinv_kernel(int n) {
    int i = blockIdx.x * blockDim.x + threadIdx.x;
    if (i < n) g_dinv[i] = rsqrtf(fmaxf((float)g_cnt[i], 1.0f));
}

// ---- prefix scan over g_cnt -> g_off (exclusive), g_cur copy ---------------
__global__ void scan1_kernel(int n) {
    __shared__ int sh[256];
    int t = threadIdx.x;
    int i = blockIdx.x * 256 + t;
    int v = (i < n) ? g_cnt[i] : 0;
    sh[t] = v;
    __syncthreads();
#pragma unroll
    for (int o = 1; o < 256; o <<= 1) {
        int add = (t >= o) ? sh[t - o] : 0;
        __syncthreads();
        sh[t] += add;
        __syncthreads();
    }
    if (i < n) g_off[i] = sh[t] - v;          // exclusive within block
    if (t == 255) g_bsum[blockIdx.x] = sh[255];
}

__global__ void scan2_kernel(int nb) {
    __shared__ int sh[256];
    int t = threadIdx.x;
    int v = (t < nb) ? g_bsum[t] : 0;
    sh[t] = v;
    __syncthreads();
#pragma unroll
    for (int o = 1; o < 256; o <<= 1) {
        int add = (t >= o) ? sh[t - o] : 0;
        __syncthreads();
        sh[t] += add;
        __syncthreads();
    }
    if (t < nb) g_bsum[t] = sh[t] - v;        // exclusive
}

__global__ void scan3_kernel(int n, int e) {
    int i = blockIdx.x * blockDim.x + threadIdx.x;
    if (i < n) {
        int o = g_off[i] + g_bsum[i >> 8];
        g_off[i] = o;
        g_cur[i] = o;
    }
    if (i == 0) g_off[n] = e;
}

__global__ void fill_kernel(const int* __restrict__ src,
                            const int* __restrict__ dst, int e) {
    int i = blockIdx.x * blockDim.x + threadIdx.x;
    if (i < e) {
        int d = dst[i];
        int pos = atomicAdd(&g_cur[d], 1);
        g_esrc[pos] = src[i];
    }
}

// ---------------------------------------------------------------------------
// Gather SpMM: fout[d] = fin[d] - dinv[d] * sum_{s in N(d)} dinv[s]*fin[s]
// One warp per dst node; lane holds float2 (64 floats = 32 lanes x 2).
// step 0: g_x -> g_f1;  step 1: g_f1 -> g_f2.
// (Buffers resolved in DEVICE code — __device__ symbols are not valid host values.)
__global__ __launch_bounds__(256) void spmm_kernel(int n, int step) {
    const float* fin = (step == 0) ? g_x : g_f1;
    float* fout      = (step == 0) ? g_f1 : g_f2;
    int w = (blockIdx.x * blockDim.x + threadIdx.x) >> 5;
    int lane = threadIdx.x & 31;
    if (w >= n) return;
    int beg = g_off[w];
    int end = g_off[w + 1];
    const float2* F = reinterpret_cast<const float2*>(fin);
    float2 acc = make_float2(0.f, 0.f);
    for (int j = beg; j < end; j++) {
        int s = __ldg(&g_esrc[j]);
        float wt = __ldg(&g_dinv[s]);
        float2 v = F[s * 32 + lane];
        acc.x = fmaf(wt, v.x, acc.x);
        acc.y = fmaf(wt, v.y, acc.y);
    }
    float wd = g_dinv[w];
    float2 xv = F[w * 32 + lane];
    float2 r = make_float2(xv.x - wd * acc.x, xv.y - wd * acc.y);
    reinterpret_cast<float2*>(fout)[w * 32 + lane] = r;
}

// ---------------------------------------------------------------------------
// GEMM1: g_x = relu(features[n,128] @ W1[64,128]^T + b1)
// 256 threads, M-tile 128, N=64. Each thread: 4 rows x 8 cols.
__global__ __launch_bounds__(256) void gemm1_kernel(
    const float* __restrict__ A, const float* __restrict__ W1,
    const float* __restrict__ b1, int n) {
    __shared__ float As[32][132];
    __shared__ float Bs[32][68];
    int t = threadIdx.x;
    int m0 = blockIdx.x * 128;
    int tx = t & 7, ty = t >> 3;       // tx: 8 col-groups, ty: 32 row-groups
    int kv = t & 7, m4 = t >> 3;       // A-load mapping

    float acc[4][8];
#pragma unroll
    for (int i = 0; i < 4; i++)
#pragma unroll
        for (int j = 0; j < 8; j++) acc[i][j] = 0.f;

    for (int k0 = 0; k0 < IN_FEATS; k0 += 32) {
#pragma unroll
        for (int i = 0; i < 4; i++) {
            int m = m4 * 4 + i;
            int gm = m0 + m;
            float4 v = make_float4(0.f, 0.f, 0.f, 0.f);
            if (gm < n)
                v = *reinterpret_cast<const float4*>(A + (size_t)gm * IN_FEATS + k0 + kv * 4);
            As[kv * 4 + 0][m] = v.x;
            As[kv * 4 + 1][m] = v.y;
            As[kv * 4 + 2][m] = v.z;
            As[kv * 4 + 3][m] = v.w;
        }
#pragma unroll
        for (int i = 0; i < 2; i++) {
            int fl = t * 2 + i;
            int nn = fl >> 3, kv2 = fl & 7;
            float4 v = *reinterpret_cast<const float4*>(W1 + (size_t)nn * IN_FEATS + k0 + kv2 * 4);
            Bs[kv2 * 4 + 0][nn] = v.x;
            Bs[kv2 * 4 + 1][nn] = v.y;
            Bs[kv2 * 4 + 2][nn] = v.z;
            Bs[kv2 * 4 + 3][nn] = v.w;
        }
        __syncthreads();
#pragma unroll
        for (int k = 0; k < 32; k++) {
            float4 a = *reinterpret_cast<float4*>(&As[k][ty * 4]);
            float4 bA = *reinterpret_cast<float4*>(&Bs[k][tx * 8]);
            float4 bB = *reinterpret_cast<float4*>(&Bs[k][tx * 8 + 4]);
            float av[4] = {a.x, a.y, a.z, a.w};
            float bv[8] = {bA.x, bA.y, bA.z, bA.w, bB.x, bB.y, bB.z, bB.w};
#pragma unroll
            for (int i = 0; i < 4; i++)
#pragma unroll
                for (int j = 0; j < 8; j++)
                    acc[i][j] = fmaf(av[i], bv[j], acc[i][j]);
        }
        __syncthreads();
    }
#pragma unroll
    for (int i = 0; i < 4; i++) {
        int gm = m0 + ty * 4 + i;
        if (gm < n) {
#pragma unroll
            for (int j = 0; j < 8; j++) {
                float v = acc[i][j] + b1[tx * 8 + j];
                g_x[(size_t)gm * HF + tx * 8 + j] = v > 0.f ? v : 0.f;
            }
        }
    }
}

// ---------------------------------------------------------------------------
// Fold thetas into W2: M[r][p*64+c] = sum_j THETA[j][p] * W2[r][j*64+c]
__global__ void buildM_kernel(const float* __restrict__ W2) {
    int t = blockIdx.x * blockDim.x + threadIdx.x;
    if (t >= HF * 192) return;
    int r = t / 192, k = t % 192;
    int p = k >> 6, c = k & 63;
    const float cA[3] = {3.0f, -3.0f, 0.75f};
    const float cB[3] = {0.0f, 3.0f, -1.5f};
    const float cC[3] = {0.0f, 0.0f, 0.75f};
    g_M[t] = cA[p] * W2[r * 192 + c]
           + cB[p] * W2[r * 192 + 64 + c]
           + cC[p] * W2[r * 192 + 128 + c];
}

// GEMM2: out = [x | f1 | f2] @ M^T + b2   (K=192)
__global__ __launch_bounds__(256) void gemm2_kernel(
    const float* __restrict__ b2, float* __restrict__ out, int n) {
    __shared__ float As[32][132];
    __shared__ float Bs[32][68];
    int t = threadIdx.x;
    int m0 = blockIdx.x * 128;
    int tx = t & 7, ty = t >> 3;
    int kv = t & 7, m4 = t >> 3;

    float acc[4][8];
#pragma unroll
    for (int i = 0; i < 4; i++)
#pragma unroll
        for (int j = 0; j < 8; j++) acc[i][j] = 0.f;

#pragma unroll
    for (int cch = 0; cch < 6; cch++) {
        const float* S = (cch < 2) ? g_x : (cch < 4) ? g_f1 : g_f2;
        int koff = (cch & 1) * 32;
#pragma unroll
        for (int i = 0; i < 4; i++) {
            int m = m4 * 4 + i;
            int gm = m0 + m;
            float4 v = make_float4(0.f, 0.f, 0.f, 0.f);
            if (gm < n)
                v = *reinterpret_cast<const float4*>(S + (size_t)gm * HF + koff + kv * 4);
            As[kv * 4 + 0][m] = v.x;
            As[kv * 4 + 1][m] = v.y;
            As[kv * 4 + 2][m] = v.z;
            As[kv * 4 + 3][m] = v.w;
        }
#pragma unroll
        for (int i = 0; i < 2; i++) {
            int fl = t * 2 + i;
            int nn = fl >> 3, kv2 = fl & 7;
            float4 v = *reinterpret_cast<const float4*>(g_M + (size_t)nn * 192 + cch * 32 + kv2 * 4);
            Bs[kv2 * 4 + 0][nn] = v.x;
            Bs[kv2 * 4 + 1][nn] = v.y;
            Bs[kv2 * 4 + 2][nn] = v.z;
            Bs[kv2 * 4 + 3][nn] = v.w;
        }
        __syncthreads();
#pragma unroll
        for (int k = 0; k < 32; k++) {
            float4 a = *reinterpret_cast<float4*>(&As[k][ty * 4]);
            float4 bA = *reinterpret_cast<float4*>(&Bs[k][tx * 8]);
            float4 bB = *reinterpret_cast<float4*>(&Bs[k][tx * 8 + 4]);
            float av[4] = {a.x, a.y, a.z, a.w};
            float bv[8] = {bA.x, bA.y, bA.z, bA.w, bB.x, bB.y, bB.z, bB.w};
#pragma unroll
            for (int i = 0; i < 4; i++)
#pragma unroll
                for (int j = 0; j < 8; j++)
                    acc[i][j] = fmaf(av[i], bv[j], acc[i][j]);
        }
        __syncthreads();
    }
#pragma unroll
    for (int i = 0; i < 4; i++) {
        int gm = m0 + ty * 4 + i;
        if (gm < n) {
#pragma unroll
            for (int j = 0; j < 8; j++)
                out[(size_t)gm * HF + tx * 8 + j] = acc[i][j] + b2[tx * 8 + j];
        }
    }
}

// ---------------------------------------------------------------------------
extern "C" void kernel_launch(void* const* d_in, const int* in_sizes, int n_in,
                              void* d_out, int out_size) {
    const float* features = (const float*)d_in[0];
    const int*   src      = (const int*)d_in[1];
    const int*   dst      = (const int*)d_in[2];
    const float* W1       = (const float*)d_in[3];
    const float* b1       = (const float*)d_in[4];
    const float* W2       = (const float*)d_in[5];
    const float* b2       = (const float*)d_in[6];
    float* out = (float*)d_out;

    int n = in_sizes[0] / IN_FEATS;   // 50000
    int e = in_sizes[1];              // 800000
    int nb = (n + 255) / 256;         // 196

    zero_cnt_kernel<<<nb, 256>>>(n);
    count_kernel<<<(e + 255) / 256, 256>>>(dst, e);
    dinv_kernel<<<nb, 256>>>(n);
    scan1_kernel<<<nb, 256>>>(n);
    scan2_kernel<<<1, 256>>>(nb);
    scan3_kernel<<<nb, 256>>>(n, e);
    fill_kernel<<<(e + 255) / 256, 256>>>(src, dst, e);

    gemm1_kernel<<<(n + 127) / 128, 256>>>(features, W1, b1, n);
    buildM_kernel<<<(HF * 192 + 255) / 256, 256>>>(W2);

    int spmm_blocks = (n + 7) / 8;    // 8 warps/block, warp per node
    spmm_kernel<<<spmm_blocks, 256>>>(n, 0);
    spmm_kernel<<<spmm_blocks, 256>>>(n, 1);

    gemm2_kernel<<<(n + 127) / 128, 256>>>(b2, out, n);
}